// round 1
// baseline (speedup 1.0000x reference)
#include <cuda_runtime.h>
#include <math.h>

// Shapes (fixed for this problem)
#define TOK   4096   // batch tokens (N)
#define DIN   4096
#define DOUT  4096
#define ELEMS ((size_t)DOUT * (size_t)DIN)   // 16777216

#define FAST_DECAY 0.95f
#define FAST_LR    0.05f
#define SLOW_DECAY 0.99f
#define SLOW_LR    0.01f
#define HOMEO_TARGET 5.0

// Scratch (allocations are forbidden; __device__ globals are the sanctioned path)
__device__ float  g_weff[ELEMS];        // 64 MB: effective weights
__device__ double g_partials[1024];     // per-block sum-of-squares partials
__device__ float  g_factor;             // homeostatic scale factor

// ---------------------------------------------------------------------------
// Kernel 1: per-row bitnet quantize + combine traces into w_eff
// One block per output row (4096 rows), 256 threads.
// ---------------------------------------------------------------------------
__global__ __launch_bounds__(256) void k_quant_combine(
    const float* __restrict__ w,
    const float* __restrict__ fast,
    const float* __restrict__ slow,
    float* __restrict__ weff)
{
    const int row = blockIdx.x;
    const size_t base = (size_t)row * DIN;
    const int tid = threadIdx.x;

    // mean(|w_row|)
    float s = 0.f;
    for (int i = tid; i < DIN; i += 256) s += fabsf(w[base + i]);
    __shared__ float red[256];
    red[tid] = s;
    __syncthreads();
    #pragma unroll
    for (int off = 128; off > 0; off >>= 1) {
        if (tid < off) red[tid] += red[tid + off];
        __syncthreads();
    }
    float scale = red[0] * (1.0f / (float)DIN);
    scale = fmaxf(scale, 1e-5f);   // jnp.clip(..., 1e-5, None)
    const float inv_scale = 1.0f / scale;

    for (int i = tid; i < DIN; i += 256) {
        const size_t idx = base + i;
        float q = rintf(w[idx] * inv_scale);       // round half-to-even == jnp.round
        q = fminf(fmaxf(q, -1.0f), 1.0f);
        weff[idx] = q * scale + 0.1f * fast[idx] + 0.05f * slow[idx];
    }
}

// ---------------------------------------------------------------------------
// Kernel 2: y = x @ w_eff^T   (NT layout: both operands K-contiguous)
// 128x128x16 tile, 256 threads, 8x8 per-thread register tile.
// ---------------------------------------------------------------------------
__global__ __launch_bounds__(256) void k_gemm_y(
    const float* __restrict__ X,      // [TOK, DIN]
    const float* __restrict__ W,      // [DOUT, DIN] (w_eff)
    float* __restrict__ Y)            // [TOK, DOUT]
{
    __shared__ float As[16][128];     // As[k][m]  (m = token rows)
    __shared__ float Bs[16][128];     // Bs[k][n]  (n = output cols)

    const int bm = blockIdx.y * 128;  // token tile
    const int bn = blockIdx.x * 128;  // d_out tile
    const int tid = threadIdx.x;
    const int ty = tid >> 4;          // 0..15
    const int tx = tid & 15;          // 0..15

    // loader mapping: 128 rows x 16 k; each thread: 2 rows (lr, lr+64), 4 k's
    const int lr = tid >> 2;          // 0..63
    const int lk = (tid & 3) << 2;    // 0,4,8,12

    float acc[8][8];
    #pragma unroll
    for (int i = 0; i < 8; i++)
        #pragma unroll
        for (int j = 0; j < 8; j++) acc[i][j] = 0.f;

    for (int k0 = 0; k0 < DIN; k0 += 16) {
        const float4 a0 = *(const float4*)&X[(size_t)(bm + lr)      * DIN + k0 + lk];
        const float4 a1 = *(const float4*)&X[(size_t)(bm + lr + 64) * DIN + k0 + lk];
        const float4 b0 = *(const float4*)&W[(size_t)(bn + lr)      * DIN + k0 + lk];
        const float4 b1 = *(const float4*)&W[(size_t)(bn + lr + 64) * DIN + k0 + lk];

        __syncthreads();   // previous tile's compute done before overwrite
        As[lk + 0][lr] = a0.x; As[lk + 1][lr] = a0.y; As[lk + 2][lr] = a0.z; As[lk + 3][lr] = a0.w;
        As[lk + 0][lr + 64] = a1.x; As[lk + 1][lr + 64] = a1.y; As[lk + 2][lr + 64] = a1.z; As[lk + 3][lr + 64] = a1.w;
        Bs[lk + 0][lr] = b0.x; Bs[lk + 1][lr] = b0.y; Bs[lk + 2][lr] = b0.z; Bs[lk + 3][lr] = b0.w;
        Bs[lk + 0][lr + 64] = b1.x; Bs[lk + 1][lr + 64] = b1.y; Bs[lk + 2][lr + 64] = b1.z; Bs[lk + 3][lr + 64] = b1.w;
        __syncthreads();

        #pragma unroll
        for (int kk = 0; kk < 16; kk++) {
            const float4 af0 = *(const float4*)&As[kk][ty * 4];
            const float4 af1 = *(const float4*)&As[kk][64 + ty * 4];
            const float4 bf0 = *(const float4*)&Bs[kk][tx * 4];
            const float4 bf1 = *(const float4*)&Bs[kk][64 + tx * 4];
            const float a[8] = {af0.x, af0.y, af0.z, af0.w, af1.x, af1.y, af1.z, af1.w};
            const float b[8] = {bf0.x, bf0.y, bf0.z, bf0.w, bf1.x, bf1.y, bf1.z, bf1.w};
            #pragma unroll
            for (int i = 0; i < 8; i++)
                #pragma unroll
                for (int j = 0; j < 8; j++)
                    acc[i][j] = fmaf(a[i], b[j], acc[i][j]);
        }
    }

    #pragma unroll
    for (int i = 0; i < 8; i++) {
        const int r = bm + ((i < 4) ? (ty * 4 + i) : (64 + ty * 4 + (i - 4)));
        float4 v0 = make_float4(acc[i][0], acc[i][1], acc[i][2], acc[i][3]);
        float4 v1 = make_float4(acc[i][4], acc[i][5], acc[i][6], acc[i][7]);
        *(float4*)&Y[(size_t)r * DOUT + bn + tx * 4]      = v0;
        *(float4*)&Y[(size_t)r * DOUT + bn + 64 + tx * 4] = v1;
    }
}

// ---------------------------------------------------------------------------
// Kernel 3: new_fast_unscaled = 0.95*fast + 0.05 * (relu(Y)^T @ X) / TOK
// TN layout: reduction over the token (row) axis; tiles load directly (no transpose).
// Also produces per-block sum-of-squares partials (deterministic order).
// ---------------------------------------------------------------------------
__global__ __launch_bounds__(256) void k_gemm_delta(
    const float* __restrict__ Y,      // [TOK, DOUT]
    const float* __restrict__ X,      // [TOK, DIN]
    const float* __restrict__ fast,   // [DOUT, DIN]
    float* __restrict__ fout)         // new_fast (unscaled), [DOUT, DIN]
{
    __shared__ float As[16][128];     // As[k][m]: relu(Y[k][bm+m])
    __shared__ float Bs[16][128];     // Bs[k][n]: X[k][bn+n]
    __shared__ double dred[256];

    const int bm = blockIdx.y * 128;  // d_out tile (rows of delta)
    const int bn = blockIdx.x * 128;  // d_in tile (cols of delta)
    const int tid = threadIdx.x;
    const int ty = tid >> 4;
    const int tx = tid & 15;

    // loader: 16 k-rows x 128 cols; each thread loads 2 float4
    const int lr = tid >> 5;          // 0..7
    const int lc = (tid & 31) << 2;   // 0,4,...,124

    float acc[8][8];
    #pragma unroll
    for (int i = 0; i < 8; i++)
        #pragma unroll
        for (int j = 0; j < 8; j++) acc[i][j] = 0.f;

    for (int k0 = 0; k0 < TOK; k0 += 16) {
        const float4 a0 = *(const float4*)&Y[(size_t)(k0 + lr)     * DOUT + bm + lc];
        const float4 a1 = *(const float4*)&Y[(size_t)(k0 + lr + 8) * DOUT + bm + lc];
        const float4 b0 = *(const float4*)&X[(size_t)(k0 + lr)     * DIN + bn + lc];
        const float4 b1 = *(const float4*)&X[(size_t)(k0 + lr + 8) * DIN + bn + lc];

        __syncthreads();
        // relu applied on the Y operand
        As[lr][lc + 0] = fmaxf(a0.x, 0.f); As[lr][lc + 1] = fmaxf(a0.y, 0.f);
        As[lr][lc + 2] = fmaxf(a0.z, 0.f); As[lr][lc + 3] = fmaxf(a0.w, 0.f);
        As[lr + 8][lc + 0] = fmaxf(a1.x, 0.f); As[lr + 8][lc + 1] = fmaxf(a1.y, 0.f);
        As[lr + 8][lc + 2] = fmaxf(a1.z, 0.f); As[lr + 8][lc + 3] = fmaxf(a1.w, 0.f);
        *(float4*)&Bs[lr][lc]     = b0;
        *(float4*)&Bs[lr + 8][lc] = b1;
        __syncthreads();

        #pragma unroll
        for (int kk = 0; kk < 16; kk++) {
            const float4 af0 = *(const float4*)&As[kk][ty * 4];
            const float4 af1 = *(const float4*)&As[kk][64 + ty * 4];
            const float4 bf0 = *(const float4*)&Bs[kk][tx * 4];
            const float4 bf1 = *(const float4*)&Bs[kk][64 + tx * 4];
            const float a[8] = {af0.x, af0.y, af0.z, af0.w, af1.x, af1.y, af1.z, af1.w};
            const float b[8] = {bf0.x, bf0.y, bf0.z, bf0.w, bf1.x, bf1.y, bf1.z, bf1.w};
            #pragma unroll
            for (int i = 0; i < 8; i++)
                #pragma unroll
                for (int j = 0; j < 8; j++)
                    acc[i][j] = fmaf(a[i], b[j], acc[i][j]);
        }
    }

    const float inv_tok = 1.0f / (float)TOK;
    double ss = 0.0;
    #pragma unroll
    for (int i = 0; i < 8; i++) {
        const int r = bm + ((i < 4) ? (ty * 4 + i) : (64 + ty * 4 + (i - 4)));
        const size_t row_base = (size_t)r * DIN;

        const float4 fa0 = *(const float4*)&fast[row_base + bn + tx * 4];
        const float4 fa1 = *(const float4*)&fast[row_base + bn + 64 + tx * 4];

        float4 v0, v1;
        v0.x = FAST_DECAY * fa0.x + FAST_LR * (acc[i][0] * inv_tok);
        v0.y = FAST_DECAY * fa0.y + FAST_LR * (acc[i][1] * inv_tok);
        v0.z = FAST_DECAY * fa0.z + FAST_LR * (acc[i][2] * inv_tok);
        v0.w = FAST_DECAY * fa0.w + FAST_LR * (acc[i][3] * inv_tok);
        v1.x = FAST_DECAY * fa1.x + FAST_LR * (acc[i][4] * inv_tok);
        v1.y = FAST_DECAY * fa1.y + FAST_LR * (acc[i][5] * inv_tok);
        v1.z = FAST_DECAY * fa1.z + FAST_LR * (acc[i][6] * inv_tok);
        v1.w = FAST_DECAY * fa1.w + FAST_LR * (acc[i][7] * inv_tok);

        *(float4*)&fout[row_base + bn + tx * 4]      = v0;
        *(float4*)&fout[row_base + bn + 64 + tx * 4] = v1;

        ss += (double)v0.x * v0.x + (double)v0.y * v0.y
            + (double)v0.z * v0.z + (double)v0.w * v0.w
            + (double)v1.x * v1.x + (double)v1.y * v1.y
            + (double)v1.z * v1.z + (double)v1.w * v1.w;
    }

    dred[tid] = ss;
    __syncthreads();
    #pragma unroll
    for (int off = 128; off > 0; off >>= 1) {
        if (tid < off) dred[tid] += dred[tid + off];
        __syncthreads();
    }
    if (tid == 0) g_partials[blockIdx.y * gridDim.x + blockIdx.x] = dred[0];
}

// ---------------------------------------------------------------------------
// Kernel 4: deterministic reduction of partials -> homeostatic factor
// ---------------------------------------------------------------------------
__global__ void k_norm_factor()
{
    __shared__ double red[256];
    const int tid = threadIdx.x;
    double s = 0.0;
    for (int i = tid; i < 1024; i += 256) s += g_partials[i];
    red[tid] = s;
    __syncthreads();
    #pragma unroll
    for (int off = 128; off > 0; off >>= 1) {
        if (tid < off) red[tid] += red[tid + off];
        __syncthreads();
    }
    if (tid == 0) {
        const double norm = sqrt(red[0]);
        g_factor = (norm > HOMEO_TARGET)
                     ? (float)(HOMEO_TARGET / (norm + 1e-6))
                     : 1.0f;
    }
}

// ---------------------------------------------------------------------------
// Kernel 5: apply homeostatic scale to new_fast (in place) and compute new_slow
// ---------------------------------------------------------------------------
__global__ __launch_bounds__(256) void k_finalize(
    const float* __restrict__ slow,
    float* __restrict__ fout,         // new_fast (scaled in place)
    float* __restrict__ sout)         // new_slow
{
    const float fac = g_factor;
    const size_t i = (size_t)blockIdx.x * blockDim.x + threadIdx.x;  // float4 index
    float4 f = ((const float4*)fout)[i];
    f.x *= fac; f.y *= fac; f.z *= fac; f.w *= fac;
    ((float4*)fout)[i] = f;
    const float4 sl = ((const float4*)slow)[i];
    float4 so;
    so.x = SLOW_DECAY * sl.x + SLOW_LR * f.x;
    so.y = SLOW_DECAY * sl.y + SLOW_LR * f.y;
    so.z = SLOW_DECAY * sl.z + SLOW_LR * f.z;
    so.w = SLOW_DECAY * sl.w + SLOW_LR * f.w;
    ((float4*)sout)[i] = so;
}

// ---------------------------------------------------------------------------
extern "C" void kernel_launch(void* const* d_in, const int* in_sizes, int n_in,
                              void* d_out, int out_size)
{
    const float* x    = (const float*)d_in[0];   // [TOK, DIN]
    const float* w    = (const float*)d_in[1];   // [DOUT, DIN]
    const float* fast = (const float*)d_in[2];   // [DOUT, DIN]
    const float* slow = (const float*)d_in[3];   // [DOUT, DIN]

    float* out   = (float*)d_out;
    float* y_out = out;                          // [TOK, DOUT]
    float* f_out = out + (size_t)TOK * DOUT;     // [DOUT, DIN]
    float* s_out = f_out + ELEMS;                // [DOUT, DIN]

    float* weff;
    cudaGetSymbolAddress((void**)&weff, g_weff);

    // 1) quantize + combine
    k_quant_combine<<<DOUT, 256>>>(w, fast, slow, weff);

    // 2) y = x @ w_eff^T
    {
        dim3 grid(DOUT / 128, TOK / 128);
        k_gemm_y<<<grid, 256>>>(x, weff, y_out);
    }

    // 3) new_fast (unscaled) = 0.95*fast + 0.05*(relu(y)^T @ x)/TOK, + sumsq partials
    {
        dim3 grid(DIN / 128, DOUT / 128);
        k_gemm_delta<<<grid, 256>>>(y_out, x, fast, f_out);
    }

    // 4) norm -> factor
    k_norm_factor<<<1, 256>>>();

    // 5) scale new_fast, compute new_slow
    k_finalize<<<(unsigned)(ELEMS / 4 / 256), 256>>>(slow, f_out, s_out);
}

// round 3
// speedup vs baseline: 1.9633x; 1.9633x over previous
#include <cuda_runtime.h>
#include <cuda_bf16.h>
#include <stdint.h>
#include <math.h>

// ---------------------------------------------------------------------------
// Shapes (fixed)
#define TOK   4096
#define DIN   4096
#define DOUT  4096
#define ELEMS ((size_t)DOUT * (size_t)DIN)

#define FAST_DECAY 0.95f
#define FAST_LR    0.05f
#define SLOW_DECAY 0.99f
#define SLOW_LR    0.01f
#define HOMEO_TARGET 5.0

// GEMM tiling: CTA 128x128x32(bf16), 8 warps (4m x 2n), warp 32x64
#define BK        32
#define NCHUNK    (4096 / BK)        // 128
#define ROW_U32   20                 // 16 u32 data + 4 pad (uint4-aligned, conflict-free)
#define TILE_U32  (128 * ROW_U32)    // 2560 u32 per operand tile
#define STAGE_U32 (4 * TILE_U32)     // Ahi, Alo, Bhi, Blo
#define DYN_SMEM  (2 * STAGE_U32 * 4)  // 81920 bytes

// ---------------------------------------------------------------------------
// Scratch (allocations forbidden; __device__ globals are sanctioned)
__device__ __nv_bfloat16 g_whi[ELEMS], g_wlo[ELEMS];     // w_eff split, K-major
__device__ __nv_bfloat16 g_xhi[ELEMS], g_xlo[ELEMS];     // X split, K-major
__device__ __nv_bfloat16 g_xthi[ELEMS], g_xtlo[ELEMS];   // X^T split   [DIN, TOK]
__device__ __nv_bfloat16 g_ythi[ELEMS], g_ytlo[ELEMS];   // relu(Y)^T   [DOUT, TOK]
__device__ double g_partials[1024];
__device__ float  g_factor;

// ---------------------------------------------------------------------------
__device__ __forceinline__ void mma_bf16(float* c, const uint32_t* a, const uint32_t* b) {
    asm volatile(
        "mma.sync.aligned.m16n8k16.row.col.f32.bf16.bf16.f32 "
        "{%0,%1,%2,%3}, {%4,%5,%6,%7}, {%8,%9}, {%0,%1,%2,%3};"
        : "+f"(c[0]), "+f"(c[1]), "+f"(c[2]), "+f"(c[3])
        : "r"(a[0]), "r"(a[1]), "r"(a[2]), "r"(a[3]), "r"(b[0]), "r"(b[1]));
}

// ---------------------------------------------------------------------------
// Kernel: per-row bitnet quantize + combine traces; split to bf16 hi/lo
__global__ __launch_bounds__(256) void k_quant_split(
    const float* __restrict__ w, const float* __restrict__ fast, const float* __restrict__ slow,
    __nv_bfloat16* __restrict__ whi, __nv_bfloat16* __restrict__ wlo)
{
    const int row = blockIdx.x;
    const size_t base = (size_t)row * DIN;
    const int tid = threadIdx.x;

    float s = 0.f;
    for (int i = tid; i < DIN; i += 256) s += fabsf(w[base + i]);
    __shared__ float red[256];
    red[tid] = s;
    __syncthreads();
    #pragma unroll
    for (int off = 128; off > 0; off >>= 1) {
        if (tid < off) red[tid] += red[tid + off];
        __syncthreads();
    }
    float scale = fmaxf(red[0] * (1.0f / (float)DIN), 1e-5f);
    const float inv_scale = 1.0f / scale;

    for (int i = tid; i < DIN; i += 256) {
        const size_t idx = base + i;
        float q = rintf(w[idx] * inv_scale);
        q = fminf(fmaxf(q, -1.0f), 1.0f);
        float v = q * scale + 0.1f * fast[idx] + 0.05f * slow[idx];
        __nv_bfloat16 h = __float2bfloat16_rn(v);
        whi[idx] = h;
        wlo[idx] = __float2bfloat16_rn(v - __bfloat162float(h));
    }
}

// ---------------------------------------------------------------------------
// Kernel: elementwise split fp32 -> bf16 hi/lo (same layout)
__global__ __launch_bounds__(256) void k_split(
    const float* __restrict__ in, __nv_bfloat16* __restrict__ hi, __nv_bfloat16* __restrict__ lo)
{
    const size_t i = ((size_t)blockIdx.x * 256 + threadIdx.x) * 4;
    float4 v = *(const float4*)(in + i);
    union { __nv_bfloat16 b[4]; uint64_t u; } H, L;
    float f[4] = {v.x, v.y, v.z, v.w};
    #pragma unroll
    for (int j = 0; j < 4; j++) {
        __nv_bfloat16 h = __float2bfloat16_rn(f[j]);
        H.b[j] = h;
        L.b[j] = __float2bfloat16_rn(f[j] - __bfloat162float(h));
    }
    *(uint64_t*)(hi + i) = H.u;
    *(uint64_t*)(lo + i) = L.u;
}

// ---------------------------------------------------------------------------
// Kernel: transpose fp32 [4096,4096] -> bf16 hi/lo transposed (optional relu)
template<bool RELU>
__global__ __launch_bounds__(256) void k_transpose_split(
    const float* __restrict__ in, __nv_bfloat16* __restrict__ ohi, __nv_bfloat16* __restrict__ olo)
{
    __shared__ float tile[32][33];
    const int x  = blockIdx.x * 32 + threadIdx.x;
    const int y0 = blockIdx.y * 32;
    #pragma unroll
    for (int j = threadIdx.y; j < 32; j += 8) {
        float v = in[(size_t)(y0 + j) * 4096 + x];
        if (RELU) v = fmaxf(v, 0.f);
        tile[j][threadIdx.x] = v;
    }
    __syncthreads();
    const int xo  = y0 + threadIdx.x;
    const int yo0 = blockIdx.x * 32;
    #pragma unroll
    for (int j = threadIdx.y; j < 32; j += 8) {
        float v = tile[threadIdx.x][j];
        __nv_bfloat16 h = __float2bfloat16_rn(v);
        ohi[(size_t)(yo0 + j) * 4096 + xo] = h;
        olo[(size_t)(yo0 + j) * 4096 + xo] = __float2bfloat16_rn(v - __bfloat162float(h));
    }
}

// ---------------------------------------------------------------------------
// bf16x3 GEMM via mma.sync (NT): D[m][n] = sum_k A[am+m][k] * B[bn+n][k]
// MODE 0: out = fp32 D (y). MODE 1: fast-trace epilogue + sumsq partials.
// ---------------------------------------------------------------------------
template<int MODE>
__global__ __launch_bounds__(256) void k_gemm_mma(
    const __nv_bfloat16* __restrict__ Ahi, const __nv_bfloat16* __restrict__ Alo,
    const __nv_bfloat16* __restrict__ Bhi, const __nv_bfloat16* __restrict__ Blo,
    const float* __restrict__ fast, float* __restrict__ out)
{
    extern __shared__ uint32_t smem[];
    __shared__ double dred[256];

    const int tid  = threadIdx.x;
    const int wid  = tid >> 5;
    const int lane = tid & 31;
    const int g    = lane >> 2;     // group id (0..7)
    const int tig  = lane & 3;      // thread-in-group

    // supertile swizzle for L2 reuse: 4 groups x (32 m-tiles x 8 n-tiles)
    const int bid   = blockIdx.x;
    const int group = bid >> 8;            // 0..3
    const int rem   = bid & 255;
    const int am  = (rem >> 3) * 128;      // A (m) row base
    const int bn  = (group * 8 + (rem & 7)) * 128;  // B (n) row base

    // warp sub-tile: 4 (m) x 2 (n)
    const int wm = (wid & 3) * 32;         // warp m offset within CTA tile
    const int wn = (wid >> 2) * 64;        // warp n offset

    const __nv_bfloat16* const srcs[4] = {Ahi, Alo, Bhi, Blo};
    const int rbase[4] = {am, am, bn, bn};

    float acc[2][8][4];
    #pragma unroll
    for (int mt = 0; mt < 2; mt++)
        #pragma unroll
        for (int nt = 0; nt < 8; nt++)
            #pragma unroll
            for (int r = 0; r < 4; r++) acc[mt][nt][r] = 0.f;

    // loader mapping: per operand tile, 512 uint4 (128 rows x 4 quads); 2 per thread
    const int lrow0 = tid >> 2,            const_q0 = 0;
    const int lq    = tid & 3;
    (void)const_q0;

    uint4 pf[8];
    // prefetch chunk 0
    #pragma unroll
    for (int op = 0; op < 4; op++) {
        #pragma unroll
        for (int j = 0; j < 2; j++) {
            const int i = tid + j * 256;
            const int row = i >> 2, q = i & 3;
            pf[op * 2 + j] = *(const uint4*)(srcs[op] + (size_t)(rbase[op] + row) * 4096 + q * 8);
        }
    }
    // commit chunk 0 into stage 0
    #pragma unroll
    for (int op = 0; op < 4; op++) {
        #pragma unroll
        for (int j = 0; j < 2; j++) {
            const int i = tid + j * 256;
            const int row = i >> 2, q = i & 3;
            *(uint4*)(smem + op * TILE_U32 + row * ROW_U32 + q * 4) = pf[op * 2 + j];
        }
    }
    (void)lrow0; (void)lq;

    for (int c = 0; c < NCHUNK; c++) {
        __syncthreads();   // stage (c&1) visible; all warps done with chunk c-1

        // prefetch chunk c+1 (gmem -> regs)
        if (c + 1 < NCHUNK) {
            const int k0 = (c + 1) * BK;
            #pragma unroll
            for (int op = 0; op < 4; op++) {
                #pragma unroll
                for (int j = 0; j < 2; j++) {
                    const int i = tid + j * 256;
                    const int row = i >> 2, q = i & 3;
                    pf[op * 2 + j] = *(const uint4*)(srcs[op] +
                        (size_t)(rbase[op] + row) * 4096 + k0 + q * 8);
                }
            }
        }

        // compute from stage c&1
        const uint32_t* stg = smem + (c & 1) * STAGE_U32;
        const uint32_t* As_hi = stg;
        const uint32_t* As_lo = stg + TILE_U32;
        const uint32_t* Bs_hi = stg + 2 * TILE_U32;
        const uint32_t* Bs_lo = stg + 3 * TILE_U32;

        #pragma unroll
        for (int ks = 0; ks < 2; ks++) {
            const int kp = ks * 8 + tig;   // u32 (k-pair) index

            uint32_t ahi[2][4], alo[2][4];
            #pragma unroll
            for (int mt = 0; mt < 2; mt++) {
                const int r0 = wm + mt * 16 + g;
                ahi[mt][0] = As_hi[(r0)     * ROW_U32 + kp];
                ahi[mt][1] = As_hi[(r0 + 8) * ROW_U32 + kp];
                ahi[mt][2] = As_hi[(r0)     * ROW_U32 + kp + 4];
                ahi[mt][3] = As_hi[(r0 + 8) * ROW_U32 + kp + 4];
                alo[mt][0] = As_lo[(r0)     * ROW_U32 + kp];
                alo[mt][1] = As_lo[(r0 + 8) * ROW_U32 + kp];
                alo[mt][2] = As_lo[(r0)     * ROW_U32 + kp + 4];
                alo[mt][3] = As_lo[(r0 + 8) * ROW_U32 + kp + 4];
            }
            uint32_t bhi[8][2], blo[8][2];
            #pragma unroll
            for (int nt = 0; nt < 8; nt++) {
                const int n0 = wn + nt * 8 + g;
                bhi[nt][0] = Bs_hi[n0 * ROW_U32 + kp];
                bhi[nt][1] = Bs_hi[n0 * ROW_U32 + kp + 4];
                blo[nt][0] = Bs_lo[n0 * ROW_U32 + kp];
                blo[nt][1] = Bs_lo[n0 * ROW_U32 + kp + 4];
            }
            #pragma unroll
            for (int mt = 0; mt < 2; mt++)
                #pragma unroll
                for (int nt = 0; nt < 8; nt++) {
                    mma_bf16(acc[mt][nt], ahi[mt], bhi[nt]);
                    mma_bf16(acc[mt][nt], ahi[mt], blo[nt]);
                    mma_bf16(acc[mt][nt], alo[mt], bhi[nt]);
                }
        }

        // store prefetched chunk c+1 into the other stage (consumed chunk c-1;
        // the top-of-loop sync guaranteed everyone finished it)
        if (c + 1 < NCHUNK) {
            uint32_t* dst = smem + ((c + 1) & 1) * STAGE_U32;
            #pragma unroll
            for (int op = 0; op < 4; op++) {
                #pragma unroll
                for (int j = 0; j < 2; j++) {
                    const int i = tid + j * 256;
                    const int row = i >> 2, q = i & 3;
                    *(uint4*)(dst + op * TILE_U32 + row * ROW_U32 + q * 4) = pf[op * 2 + j];
                }
            }
        }
    }

    // epilogue
    double ss = 0.0;
    const float inv_tok = 1.0f / (float)TOK;
    #pragma unroll
    for (int mt = 0; mt < 2; mt++) {
        const int r0 = am + wm + mt * 16 + g;
        #pragma unroll
        for (int nt = 0; nt < 8; nt++) {
            const int col = bn + wn + nt * 8 + tig * 2;
            #pragma unroll
            for (int half = 0; half < 2; half++) {
                const int r = r0 + half * 8;
                const float d0 = acc[mt][nt][half * 2 + 0];
                const float d1 = acc[mt][nt][half * 2 + 1];
                const size_t o = (size_t)r * 4096 + col;
                if (MODE == 0) {
                    *(float2*)(out + o) = make_float2(d0, d1);
                } else {
                    const float2 fa = *(const float2*)(fast + o);
                    float2 v;
                    v.x = FAST_DECAY * fa.x + FAST_LR * (d0 * inv_tok);
                    v.y = FAST_DECAY * fa.y + FAST_LR * (d1 * inv_tok);
                    *(float2*)(out + o) = v;
                    ss += (double)v.x * v.x + (double)v.y * v.y;
                }
            }
        }
    }
    if (MODE == 1) {
        dred[tid] = ss;
        __syncthreads();
        #pragma unroll
        for (int off = 128; off > 0; off >>= 1) {
            if (tid < off) dred[tid] += dred[tid + off];
            __syncthreads();
        }
        if (tid == 0) g_partials[blockIdx.x] = dred[0];
    }
}

// ---------------------------------------------------------------------------
__global__ void k_norm_factor()
{
    __shared__ double red[256];
    const int tid = threadIdx.x;
    double s = 0.0;
    for (int i = tid; i < 1024; i += 256) s += g_partials[i];
    red[tid] = s;
    __syncthreads();
    #pragma unroll
    for (int off = 128; off > 0; off >>= 1) {
        if (tid < off) red[tid] += red[tid + off];
        __syncthreads();
    }
    if (tid == 0) {
        const double norm = sqrt(red[0]);
        g_factor = (norm > HOMEO_TARGET) ? (float)(HOMEO_TARGET / (norm + 1e-6)) : 1.0f;
    }
}

__global__ __launch_bounds__(256) void k_finalize(
    const float* __restrict__ slow, float* __restrict__ fout, float* __restrict__ sout)
{
    const float fac = g_factor;
    const size_t i = (size_t)blockIdx.x * blockDim.x + threadIdx.x;
    float4 f = ((const float4*)fout)[i];
    f.x *= fac; f.y *= fac; f.z *= fac; f.w *= fac;
    ((float4*)fout)[i] = f;
    const float4 sl = ((const float4*)slow)[i];
    float4 so;
    so.x = SLOW_DECAY * sl.x + SLOW_LR * f.x;
    so.y = SLOW_DECAY * sl.y + SLOW_LR * f.y;
    so.z = SLOW_DECAY * sl.z + SLOW_LR * f.z;
    so.w = SLOW_DECAY * sl.w + SLOW_LR * f.w;
    ((float4*)sout)[i] = so;
}

// ---------------------------------------------------------------------------
extern "C" void kernel_launch(void* const* d_in, const int* in_sizes, int n_in,
                              void* d_out, int out_size)
{
    const float* x    = (const float*)d_in[0];
    const float* w    = (const float*)d_in[1];
    const float* fast = (const float*)d_in[2];
    const float* slow = (const float*)d_in[3];

    float* out   = (float*)d_out;
    float* y_out = out;
    float* f_out = out + (size_t)TOK * DOUT;
    float* s_out = f_out + ELEMS;

    __nv_bfloat16 *whi, *wlo, *xhi, *xlo, *xthi, *xtlo, *ythi, *ytlo;
    cudaGetSymbolAddress((void**)&whi,  g_whi);
    cudaGetSymbolAddress((void**)&wlo,  g_wlo);
    cudaGetSymbolAddress((void**)&xhi,  g_xhi);
    cudaGetSymbolAddress((void**)&xlo,  g_xlo);
    cudaGetSymbolAddress((void**)&xthi, g_xthi);
    cudaGetSymbolAddress((void**)&xtlo, g_xtlo);
    cudaGetSymbolAddress((void**)&ythi, g_ythi);
    cudaGetSymbolAddress((void**)&ytlo, g_ytlo);

    static bool attr_done = false;
    if (!attr_done) {
        cudaFuncSetAttribute(k_gemm_mma<0>, cudaFuncAttributeMaxDynamicSharedMemorySize, DYN_SMEM);
        cudaFuncSetAttribute(k_gemm_mma<1>, cudaFuncAttributeMaxDynamicSharedMemorySize, DYN_SMEM);
        attr_done = true;
    }

    // 1) w_eff = quantize(w) + 0.1*fast + 0.05*slow -> bf16 hi/lo
    k_quant_split<<<DOUT, 256>>>(w, fast, slow, whi, wlo);
    // 2) X -> bf16 hi/lo (K-major, for GEMM1)
    k_split<<<(unsigned)(ELEMS / 4 / 256), 256>>>(x, xhi, xlo);
    // 3) X^T -> bf16 hi/lo (for GEMM2 B operand)
    k_transpose_split<false><<<dim3(128, 128), dim3(32, 8)>>>(x, xthi, xtlo);
    // 4) Y = X @ w_eff^T
    k_gemm_mma<0><<<1024, 256, DYN_SMEM>>>(xhi, xlo, whi, wlo, nullptr, y_out);
    // 5) relu(Y)^T -> bf16 hi/lo (for GEMM2 A operand)
    k_transpose_split<true><<<dim3(128, 128), dim3(32, 8)>>>(y_out, ythi, ytlo);
    // 6) new_fast (unscaled) = 0.95*fast + 0.05*(reluY^T @ X)/TOK, + partials
    k_gemm_mma<1><<<1024, 256, DYN_SMEM>>>(ythi, ytlo, xthi, xtlo, fast, f_out);
    // 7) norm -> factor
    k_norm_factor<<<1, 256>>>();
    // 8) scale fast, compute slow
    k_finalize<<<(unsigned)(ELEMS / 4 / 256), 256>>>(slow, f_out, s_out);
}

// round 4
// speedup vs baseline: 2.0258x; 1.0318x over previous
#include <cuda_runtime.h>
#include <cuda_bf16.h>
#include <stdint.h>
#include <math.h>

// ---------------------------------------------------------------------------
// Shapes (fixed)
#define TOK   4096
#define DIN   4096
#define DOUT  4096
#define ELEMS ((size_t)DOUT * (size_t)DIN)

#define FAST_DECAY 0.95f
#define FAST_LR    0.05f
#define SLOW_DECAY 0.99f
#define SLOW_LR    0.01f
#define HOMEO_TARGET 5.0

// CTA tile 128x128x32(bf16), 8 warps (4m x 2n), warp tile 32x64
#define BK      32
#define NCHUNK  (4096 / BK)          // 128
#define DYN_SMEM 81920               // max of the two layouts (2 stages x 4 tiles)

// ---------------------------------------------------------------------------
// Scratch
__device__ __nv_bfloat16 g_whi[ELEMS], g_wlo[ELEMS];     // w_eff split, K-major
__device__ __nv_bfloat16 g_xhi[ELEMS], g_xlo[ELEMS];     // X split [TOK, DIN]
__device__ __nv_bfloat16 g_yrhi[ELEMS], g_yrlo[ELEMS];   // relu(Y) split [TOK, DOUT]
__device__ double g_partials[1024];
__device__ float  g_factor;

// ---------------------------------------------------------------------------
__device__ __forceinline__ uint32_t smem_u32(const void* p) {
    uint32_t a;
    asm("{ .reg .u64 t; cvta.to.shared.u64 t, %1; cvt.u32.u64 %0, t; }" : "=r"(a) : "l"(p));
    return a;
}
__device__ __forceinline__ void mma_bf16(float* c, const uint32_t* a, const uint32_t* b) {
    asm volatile(
        "mma.sync.aligned.m16n8k16.row.col.f32.bf16.bf16.f32 "
        "{%0,%1,%2,%3}, {%4,%5,%6,%7}, {%8,%9}, {%0,%1,%2,%3};"
        : "+f"(c[0]), "+f"(c[1]), "+f"(c[2]), "+f"(c[3])
        : "r"(a[0]), "r"(a[1]), "r"(a[2]), "r"(a[3]), "r"(b[0]), "r"(b[1]));
}
#define LDSM4(R, A) \
    asm volatile("ldmatrix.sync.aligned.m8n8.x4.shared.b16 {%0,%1,%2,%3}, [%4];" \
        : "=r"((R)[0]), "=r"((R)[1]), "=r"((R)[2]), "=r"((R)[3]) : "r"(A))
#define LDSM4T(R, A) \
    asm volatile("ldmatrix.sync.aligned.m8n8.x4.trans.shared.b16 {%0,%1,%2,%3}, [%4];" \
        : "=r"((R)[0]), "=r"((R)[1]), "=r"((R)[2]), "=r"((R)[3]) : "r"(A))

// ---------------------------------------------------------------------------
// Kernel: per-row bitnet quantize + combine traces; split to bf16 hi/lo
__global__ __launch_bounds__(256) void k_quant_split(
    const float* __restrict__ w, const float* __restrict__ fast, const float* __restrict__ slow,
    __nv_bfloat16* __restrict__ whi, __nv_bfloat16* __restrict__ wlo)
{
    const int row = blockIdx.x;
    const size_t base = (size_t)row * DIN;
    const int tid = threadIdx.x;

    float s = 0.f;
    for (int i = tid; i < DIN; i += 256) s += fabsf(w[base + i]);
    __shared__ float red[256];
    red[tid] = s;
    __syncthreads();
    #pragma unroll
    for (int off = 128; off > 0; off >>= 1) {
        if (tid < off) red[tid] += red[tid + off];
        __syncthreads();
    }
    float scale = fmaxf(red[0] * (1.0f / (float)DIN), 1e-5f);
    const float inv_scale = 1.0f / scale;

    for (int i = tid; i < DIN; i += 256) {
        const size_t idx = base + i;
        float q = rintf(w[idx] * inv_scale);
        q = fminf(fmaxf(q, -1.0f), 1.0f);
        float v = q * scale + 0.1f * fast[idx] + 0.05f * slow[idx];
        __nv_bfloat16 h = __float2bfloat16_rn(v);
        whi[idx] = h;
        wlo[idx] = __float2bfloat16_rn(v - __bfloat162float(h));
    }
}

// ---------------------------------------------------------------------------
// Kernel: elementwise split fp32 -> bf16 hi/lo
__global__ __launch_bounds__(256) void k_split(
    const float* __restrict__ in, __nv_bfloat16* __restrict__ hi, __nv_bfloat16* __restrict__ lo)
{
    const size_t i = ((size_t)blockIdx.x * 256 + threadIdx.x) * 4;
    float4 v = *(const float4*)(in + i);
    union { __nv_bfloat16 b[4]; uint64_t u; } H, L;
    float f[4] = {v.x, v.y, v.z, v.w};
    #pragma unroll
    for (int j = 0; j < 4; j++) {
        __nv_bfloat16 h = __float2bfloat16_rn(f[j]);
        H.b[j] = h;
        L.b[j] = __float2bfloat16_rn(f[j] - __bfloat162float(h));
    }
    *(uint64_t*)(hi + i) = H.u;
    *(uint64_t*)(lo + i) = L.u;
}

// ---------------------------------------------------------------------------
// bf16x3 GEMM via mma.sync + ldmatrix.
// MODE 0 (NT): D[m][n] = sum_k A[am+m][k]*B[bn+n][k].
//   Operand tiles [row][k] (pitch 80B). Epilogue: write y fp32 + relu-split bf16.
// MODE 1 (TT via ldmatrix.trans): D[m][n] = sum_k A[k][am+m]*B[k][bn+n].
//   Operand tiles [k][col] (pitch 272B). Epilogue: fast-trace EMA + sumsq partials.
// ---------------------------------------------------------------------------
template<int MODE>
__global__ __launch_bounds__(256) void k_gemm_mma(
    const __nv_bfloat16* __restrict__ Ahi, const __nv_bfloat16* __restrict__ Alo,
    const __nv_bfloat16* __restrict__ Bhi, const __nv_bfloat16* __restrict__ Blo,
    const float* __restrict__ fast, float* __restrict__ out,
    __nv_bfloat16* __restrict__ ohi, __nv_bfloat16* __restrict__ olo)
{
    constexpr bool TRANS = (MODE == 1);
    constexpr int PITCH = TRANS ? 68 : 20;           // u32 per smem row
    constexpr int ROWS  = TRANS ? 32 : 128;
    constexpr int TILEU = ROWS * PITCH;              // u32 per operand tile
    constexpr int STAGEU = 4 * TILEU;

    extern __shared__ uint32_t smem[];
    __shared__ double dred[256];

    const int tid  = threadIdx.x;
    const int lane = tid & 31;
    const int wid  = tid >> 5;
    const int g    = lane >> 2;
    const int tig  = lane & 3;

    // supertile swizzle: 4 groups x (32 m-tiles x 8 n-tiles)
    const int bid   = blockIdx.x;
    const int group = bid >> 8;
    const int rem   = bid & 255;
    const int am  = (rem >> 3) * 128;
    const int bn  = (group * 8 + (rem & 7)) * 128;

    const int wm = (wid & 3) * 32;
    const int wn = (wid >> 2) * 64;

    const __nv_bfloat16* const srcs[4] = {Ahi, Alo, Bhi, Blo};
    const int cbase[4] = {am, am, bn, bn};

    const uint32_t sm0 = smem_u32(smem);

    // per-lane ldmatrix base offsets (bytes within a tile)
    uint32_t a_base, b_base;
    if (!TRANS) {
        const int ld_row = ((lane >> 3) & 1) * 8 + (lane & 7);
        const int ld_kb  = (lane >> 4) * 16;
        a_base = (uint32_t)((wm + ld_row) * 80 + ld_kb);
        b_base = (uint32_t)((wn + ld_row) * 80 + ld_kb);
    } else {
        const int ld_kr = (lane >> 4) * 8 + (lane & 7);
        const int ld_cb = ((lane >> 3) & 1) * 16;
        a_base = (uint32_t)(ld_kr * 272 + wm * 2 + ld_cb);
        b_base = (uint32_t)(ld_kr * 272 + wn * 2 + ld_cb);
    }

    float acc[2][8][4];
    #pragma unroll
    for (int mt = 0; mt < 2; mt++)
        #pragma unroll
        for (int nt = 0; nt < 8; nt++)
            #pragma unroll
            for (int r = 0; r < 4; r++) acc[mt][nt][r] = 0.f;

    uint4 pf[8];
    // ---- prefetch + commit chunk 0 ----
    #pragma unroll
    for (int op = 0; op < 4; op++)
        #pragma unroll
        for (int j = 0; j < 2; j++) {
            const int i = tid + j * 256;
            if (!TRANS) {
                const int row = i >> 2, q = i & 3;
                pf[op * 2 + j] = *(const uint4*)(srcs[op] + (size_t)(cbase[op] + row) * 4096 + q * 8);
            } else {
                const int row = i >> 4, q = i & 15;
                pf[op * 2 + j] = *(const uint4*)(srcs[op] + (size_t)row * 4096 + cbase[op] + q * 8);
            }
        }
    #pragma unroll
    for (int op = 0; op < 4; op++)
        #pragma unroll
        for (int j = 0; j < 2; j++) {
            const int i = tid + j * 256;
            if (!TRANS) {
                const int row = i >> 2, q = i & 3;
                *(uint4*)(smem + op * TILEU + row * PITCH + q * 4) = pf[op * 2 + j];
            } else {
                const int row = i >> 4, q = i & 15;
                *(uint4*)(smem + op * TILEU + row * PITCH + q * 4) = pf[op * 2 + j];
            }
        }

    for (int c = 0; c < NCHUNK; c++) {
        __syncthreads();

        // prefetch chunk c+1
        if (c + 1 < NCHUNK) {
            const int k0 = (c + 1) * BK;
            #pragma unroll
            for (int op = 0; op < 4; op++)
                #pragma unroll
                for (int j = 0; j < 2; j++) {
                    const int i = tid + j * 256;
                    if (!TRANS) {
                        const int row = i >> 2, q = i & 3;
                        pf[op * 2 + j] = *(const uint4*)(srcs[op] +
                            (size_t)(cbase[op] + row) * 4096 + k0 + q * 8);
                    } else {
                        const int row = i >> 4, q = i & 15;
                        pf[op * 2 + j] = *(const uint4*)(srcs[op] +
                            (size_t)(k0 + row) * 4096 + cbase[op] + q * 8);
                    }
                }
        }

        // compute from stage c&1
        const uint32_t stg = sm0 + (uint32_t)((c & 1) * STAGEU * 4);
        #pragma unroll
        for (int ks = 0; ks < 2; ks++) {
            // A fragments: [mt][term hi/lo][4]
            uint32_t a[2][2][4];
            #pragma unroll
            for (int mt = 0; mt < 2; mt++)
                #pragma unroll
                for (int t = 0; t < 2; t++) {
                    uint32_t addr;
                    if (!TRANS) addr = stg + t * (TILEU * 4) + a_base + mt * 1280 + ks * 32;
                    else        addr = stg + t * (TILEU * 4) + a_base + mt * 32 + ks * 4352;
                    if (!TRANS) { LDSM4(a[mt][t], addr); } else { LDSM4T(a[mt][t], addr); }
                }
            // B fragments per pair (nt = 2p, 2p+1)
            #pragma unroll
            for (int p = 0; p < 4; p++) {
                uint32_t bh[4], bl[4];
                uint32_t addrh, addrl;
                if (!TRANS) {
                    addrh = stg + 2 * (TILEU * 4) + b_base + p * 1280 + ks * 32;
                    addrl = stg + 3 * (TILEU * 4) + b_base + p * 1280 + ks * 32;
                    LDSM4(bh, addrh); LDSM4(bl, addrl);
                } else {
                    addrh = stg + 2 * (TILEU * 4) + b_base + p * 32 + ks * 4352;
                    addrl = stg + 3 * (TILEU * 4) + b_base + p * 32 + ks * 4352;
                    LDSM4T(bh, addrh); LDSM4T(bl, addrl);
                }
                uint32_t bh0[2] = {bh[0], bh[2]}, bh1[2] = {bh[1], bh[3]};
                uint32_t bl0[2] = {bl[0], bl[2]}, bl1[2] = {bl[1], bl[3]};
                #pragma unroll
                for (int mt = 0; mt < 2; mt++) {
                    mma_bf16(acc[mt][2 * p],     a[mt][0], bh0);
                    mma_bf16(acc[mt][2 * p],     a[mt][0], bl0);
                    mma_bf16(acc[mt][2 * p],     a[mt][1], bh0);
                    mma_bf16(acc[mt][2 * p + 1], a[mt][0], bh1);
                    mma_bf16(acc[mt][2 * p + 1], a[mt][0], bl1);
                    mma_bf16(acc[mt][2 * p + 1], a[mt][1], bh1);
                }
            }
        }

        // commit chunk c+1
        if (c + 1 < NCHUNK) {
            uint32_t* dst = smem + ((c + 1) & 1) * STAGEU;
            #pragma unroll
            for (int op = 0; op < 4; op++)
                #pragma unroll
                for (int j = 0; j < 2; j++) {
                    const int i = tid + j * 256;
                    const int row = TRANS ? (i >> 4) : (i >> 2);
                    const int q   = TRANS ? (i & 15) : (i & 3);
                    *(uint4*)(dst + op * TILEU + row * PITCH + q * 4) = pf[op * 2 + j];
                }
        }
    }

    // ---- epilogue ----
    double ss = 0.0;
    const float inv_tok = 1.0f / (float)TOK;
    #pragma unroll
    for (int mt = 0; mt < 2; mt++) {
        const int r0 = am + wm + mt * 16 + g;
        #pragma unroll
        for (int nt = 0; nt < 8; nt++) {
            const int col = bn + wn + nt * 8 + tig * 2;
            #pragma unroll
            for (int half = 0; half < 2; half++) {
                const int r = r0 + half * 8;
                const float d0 = acc[mt][nt][half * 2 + 0];
                const float d1 = acc[mt][nt][half * 2 + 1];
                const size_t o = (size_t)r * 4096 + col;
                if (MODE == 0) {
                    *(float2*)(out + o) = make_float2(d0, d1);
                    // relu + bf16 hi/lo split for GEMM2's A operand
                    const float r0f = fmaxf(d0, 0.f), r1f = fmaxf(d1, 0.f);
                    union { __nv_bfloat16 b[2]; uint32_t u; } H, L;
                    H.b[0] = __float2bfloat16_rn(r0f);
                    H.b[1] = __float2bfloat16_rn(r1f);
                    L.b[0] = __float2bfloat16_rn(r0f - __bfloat162float(H.b[0]));
                    L.b[1] = __float2bfloat16_rn(r1f - __bfloat162float(H.b[1]));
                    *(uint32_t*)(ohi + o) = H.u;
                    *(uint32_t*)(olo + o) = L.u;
                } else {
                    const float2 fa = *(const float2*)(fast + o);
                    float2 v;
                    v.x = FAST_DECAY * fa.x + FAST_LR * (d0 * inv_tok);
                    v.y = FAST_DECAY * fa.y + FAST_LR * (d1 * inv_tok);
                    *(float2*)(out + o) = v;
                    ss += (double)v.x * v.x + (double)v.y * v.y;
                }
            }
        }
    }
    if (MODE == 1) {
        dred[tid] = ss;
        __syncthreads();
        #pragma unroll
        for (int off = 128; off > 0; off >>= 1) {
            if (tid < off) dred[tid] += dred[tid + off];
            __syncthreads();
        }
        if (tid == 0) g_partials[blockIdx.x] = dred[0];
    }
}

// ---------------------------------------------------------------------------
__global__ void k_norm_factor()
{
    __shared__ double red[256];
    const int tid = threadIdx.x;
    double s = 0.0;
    for (int i = tid; i < 1024; i += 256) s += g_partials[i];
    red[tid] = s;
    __syncthreads();
    #pragma unroll
    for (int off = 128; off > 0; off >>= 1) {
        if (tid < off) red[tid] += red[tid + off];
        __syncthreads();
    }
    if (tid == 0) {
        const double norm = sqrt(red[0]);
        g_factor = (norm > HOMEO_TARGET) ? (float)(HOMEO_TARGET / (norm + 1e-6)) : 1.0f;
    }
}

__global__ __launch_bounds__(256) void k_finalize(
    const float* __restrict__ slow, float* __restrict__ fout, float* __restrict__ sout)
{
    const float fac = g_factor;
    const size_t i = (size_t)blockIdx.x * blockDim.x + threadIdx.x;
    float4 f = ((const float4*)fout)[i];
    f.x *= fac; f.y *= fac; f.z *= fac; f.w *= fac;
    ((float4*)fout)[i] = f;
    const float4 sl = ((const float4*)slow)[i];
    float4 so;
    so.x = SLOW_DECAY * sl.x + SLOW_LR * f.x;
    so.y = SLOW_DECAY * sl.y + SLOW_LR * f.y;
    so.z = SLOW_DECAY * sl.z + SLOW_LR * f.z;
    so.w = SLOW_DECAY * sl.w + SLOW_LR * f.w;
    ((float4*)sout)[i] = so;
}

// ---------------------------------------------------------------------------
extern "C" void kernel_launch(void* const* d_in, const int* in_sizes, int n_in,
                              void* d_out, int out_size)
{
    const float* x    = (const float*)d_in[0];
    const float* w    = (const float*)d_in[1];
    const float* fast = (const float*)d_in[2];
    const float* slow = (const float*)d_in[3];

    float* out   = (float*)d_out;
    float* y_out = out;
    float* f_out = out + (size_t)TOK * DOUT;
    float* s_out = f_out + ELEMS;

    __nv_bfloat16 *whi, *wlo, *xhi, *xlo, *yrhi, *yrlo;
    cudaGetSymbolAddress((void**)&whi,  g_whi);
    cudaGetSymbolAddress((void**)&wlo,  g_wlo);
    cudaGetSymbolAddress((void**)&xhi,  g_xhi);
    cudaGetSymbolAddress((void**)&xlo,  g_xlo);
    cudaGetSymbolAddress((void**)&yrhi, g_yrhi);
    cudaGetSymbolAddress((void**)&yrlo, g_yrlo);

    static bool attr_done = false;
    if (!attr_done) {
        cudaFuncSetAttribute(k_gemm_mma<0>, cudaFuncAttributeMaxDynamicSharedMemorySize, DYN_SMEM);
        cudaFuncSetAttribute(k_gemm_mma<1>, cudaFuncAttributeMaxDynamicSharedMemorySize, DYN_SMEM);
        attr_done = true;
    }

    // 1) w_eff = quantize(w) + 0.1*fast + 0.05*slow -> bf16 hi/lo
    k_quant_split<<<DOUT, 256>>>(w, fast, slow, whi, wlo);
    // 2) X -> bf16 hi/lo (used by BOTH GEMMs)
    k_split<<<(unsigned)(ELEMS / 4 / 256), 256>>>(x, xhi, xlo);
    // 3) Y = X @ w_eff^T; epilogue emits relu(Y) bf16 hi/lo
    k_gemm_mma<0><<<1024, 256, DYN_SMEM>>>(xhi, xlo, whi, wlo, nullptr, y_out, yrhi, yrlo);
    // 4) new_fast (unscaled) = 0.95*fast + 0.05*(reluY^T @ X)/TOK, + partials
    k_gemm_mma<1><<<1024, 256, DYN_SMEM>>>(yrhi, yrlo, xhi, xlo, fast, f_out, nullptr, nullptr);
    // 5) norm -> factor
    k_norm_factor<<<1, 256>>>();
    // 6) scale fast, compute slow
    k_finalize<<<(unsigned)(ELEMS / 4 / 256), 256>>>(slow, f_out, s_out);
}